// round 16
// baseline (speedup 1.0000x reference)
#include <cuda_runtime.h>

#define TSTEPS 64
#define BSZ 1024
#define ROWS_PER_CTA 8
#define CTA_THREADS 512
#define GRID_CTAS 128

// ---- smem offsets (bytes) ---- (NO overlay: t-phase and main phase disjoint)
#define OFF_WHHT   0        // float[64][256] 64KB   (t-phase)
#define OFF_TCF    65536    // float[64][64]  16KB   per-step t-const (persistent)
#define OFF_WTF    81920    // 16KB (t-phase)
#define OFF_WMT    98304    // 16KB (t-phase)
#define OFF_WMO    114688   // 16KB (t-phase, read by fold)
#define OFF_TSCR   131072   // 4KB  (t-phase scratch)
#define OFF_WCS    135168   // float[64*68] 17408B  Wcomb scratch; later t1c[64][32] 8KB
#define OFF_W1PK   152576   // float4[512]  8KB   W1C = W1@Wcomb, packed over k-quads
#define OFF_W2S    160768   // float[1024]  4KB
#define OFF_HSH    164864   // float[2][8][72] 4608B
#define OFF_PSUM   169472   // float[8][32] 1KB
#define OFF_RING   170496   // float[3][8][2] 192B
#define OFF_OBS    170688   // float[8][16] 512B
#define SMEM_BYTES 171264

#define HSTRIDE 72
#define HBUF    576
#define WCSTRIDE 68

#define BARSYNC(id) asm volatile("bar.sync %0, 256;" :: "r"(id) : "memory")

__device__ __forceinline__ float sigf(float x) { return 1.0f / (1.0f + __expf(-x)); }
__device__ __forceinline__ float tanha(float x) { return 2.0f / (1.0f + __expf(-2.0f * x)) - 1.0f; }
__device__ __forceinline__ float lrelu(float v) { return v >= 0.0f ? v : 0.1f * v; }

// hardware tanh (single MUFU-class instruction, sm_75+)
__device__ __forceinline__ float tanhap(float x) {
    float y;
    asm("tanh.approx.f32 %0, %1;" : "=f"(y) : "f"(x));
    return y;
}

// packed f32x2 helpers (paired-k accumulation)
__device__ __forceinline__ void fma2(unsigned long long& a, unsigned long long w, unsigned long long h) {
    asm("fma.rn.f32x2 %0, %1, %2, %0;" : "+l"(a) : "l"(w), "l"(h));
}
__device__ __forceinline__ float2 upk(unsigned long long v) {
    float2 f;
    asm("mov.b64 {%0, %1}, %2;" : "=f"(f.x), "=f"(f.y) : "l"(v));
    return f;
}

__global__ void __launch_bounds__(CTA_THREADS, 1) navnet_fused_kernel(
    const float* __restrict__ obsv,
    const float* __restrict__ Wih_o, const float* __restrict__ Whh_o,
    const float* __restrict__ bih_o, const float* __restrict__ bhh_o,
    const float* __restrict__ Whh_t, const float* __restrict__ bih_t,
    const float* __restrict__ bhh_t, const float* __restrict__ Wof,
    const float* __restrict__ bof, const float* __restrict__ Wtf,
    const float* __restrict__ btf, const float* __restrict__ Wmix,
    const float* __restrict__ bmix,
    const float* __restrict__ W1, const float* __restrict__ b1,
    const float* __restrict__ W2, const float* __restrict__ b2,
    const float* __restrict__ W3, const float* __restrict__ b3,
    float* __restrict__ out, int out_size)
{
    extern __shared__ char smem[];
    const int tid = threadIdx.x;

    // t-phase pointers
    float*  WhhtT  = (float*)(smem + OFF_WHHT);
    float*  tcf    = (float*)(smem + OFF_TCF);
    float*  WtfT   = (float*)(smem + OFF_WTF);
    float*  WmixTT = (float*)(smem + OFF_WMT);
    float*  WmixOT = (float*)(smem + OFF_WMO);
    float*  tscr   = (float*)(smem + OFF_TSCR);
    float*  h_t    = tscr;
    float*  c_t    = tscr + 64;
    float*  gates  = tscr + 128;
    float*  tsv    = tscr + 384;
    float*  part   = tscr + 512;
    float*  btg    = tscr + 768;

    // main-phase pointers
    float*  wcs   = (float*)(smem + OFF_WCS);   // Wcomb scratch (pre-join), then t1c
    float*  t1cs  = (float*)(smem + OFF_WCS);   // [s][i] stride 32 (post-join)
    float4* w1pk  = (float4*)(smem + OFF_W1PK); // W1C packed [k4][i]
    float*  w2s   = (float*)(smem + OFF_W2S);
    float*  hsh   = (float*)(smem + OFF_HSH);
    float*  psum  = (float*)(smem + OFF_PSUM);
    float*  ring  = (float*)(smem + OFF_RING);
    float*  obssh = (float*)(smem + OFF_OBS);

    // =========================================================
    // Phase 1 (all 512): stage t-branch inputs
    // =========================================================
    for (int i = tid; i < 16384; i += CTA_THREADS) {
        int r = i >> 6, k = i & 63;
        WhhtT[k * 256 + r] = Whh_t[i];
    }
    for (int i = tid; i < 4096; i += CTA_THREADS) {
        int j = i >> 6, k = i & 63;
        WtfT[k * 64 + j]   = Wtf[i];
        WmixTT[k * 64 + j] = Wmix[j * 128 + k];
        WmixOT[k * 64 + j] = Wmix[j * 128 + 64 + k];
    }
    if (tid < 256) btg[tid] = bih_t[tid] + bhh_t[tid];
    if (tid < 64) { h_t[tid] = 0.f; c_t[tid] = 0.f; }
    float btf_r  = (tid < 64) ? btf[tid]  : 0.f;
    float bmix_r = (tid < 64) ? bmix[tid] : 0.f;
    __syncthreads();

    if (tid < 256) {
        int j = tid & 63, qt = tid >> 6;
        float p = 0.f;
#pragma unroll
        for (int q = 0; q < 16; q++)
            p = fmaf(WmixOT[(qt * 16 + q) * 64 + j], bof[qt * 16 + q], p);
        part[tid] = p;
    }
    __syncthreads();
    float bmixsum_r = 0.f;
    if (tid < 64)
        bmixsum_r = bmix_r + part[tid] + part[64 + tid] + part[128 + tid] + part[192 + tid];
    __syncthreads();

    // =========================================================
    // Phase 2 (SPLIT): warps 0-7 run t-scan; warps 8-15 stage main-phase smem
    // =========================================================
    if (tid < 256) {
        const float bt = btg[tid];
        const int j = tid & 63, qt = (tid >> 6) & 3;
        for (int s = 0; s < TSTEPS; s++) {
            float a = bt;
#pragma unroll 8
            for (int k = 0; k < 64; k++) a = fmaf(WhhtT[k * 256 + tid], h_t[k], a);
            gates[tid] = a;
            BARSYNC(3);
            if (tid < 64) {
                float i_ = sigf(gates[tid]), f_ = sigf(gates[64 + tid]);
                float g_ = tanha(gates[128 + tid]), o_ = sigf(gates[192 + tid]);
                float cn = f_ * c_t[tid] + i_ * g_;
                c_t[tid] = cn;
                h_t[tid] = o_ * tanha(cn);
            }
            BARSYNC(3);
            {
                float p = 0.f;
#pragma unroll
                for (int k = 0; k < 16; k++)
                    p = fmaf(WtfT[(qt * 16 + k) * 64 + j], h_t[qt * 16 + k], p);
                part[tid] = p;
            }
            BARSYNC(3);
            if (tid < 64) tsv[tid] = btf_r + part[tid] + part[64 + tid] + part[128 + tid] + part[192 + tid];
            BARSYNC(3);
            {
                float p = 0.f;
#pragma unroll
                for (int k = 0; k < 16; k++)
                    p = fmaf(WmixTT[(qt * 16 + k) * 64 + j], tsv[qt * 16 + k], p);
                part[tid] = p;
            }
            BARSYNC(3);
            if (tid < 64)
                tcf[s * 64 + tid] = bmixsum_r + part[tid] + part[64 + tid] + part[128 + tid] + part[192 + tid];
            // 6th barrier removed: next iteration's `part` writes happen only after
            // two BARSYNC(3)s, so the tcf-writer's reads of `part` are ordered.
        }
    } else {
        const int tid2 = tid - 256;
        // ---- Wcomb fold (scratch; consumed by W1C fold below) ----
        for (int idx = tid2; idx < 4096; idx += 256) {
            int j = idx >> 6, k = idx & 63;
            float s = 0.f;
#pragma unroll 8
            for (int q = 0; q < 64; q++)
                s = fmaf(WmixOT[q * 64 + j], Wof[q * 64 + k], s);
            wcs[j * WCSTRIDE + k] = s;
        }
        for (int idx = tid2; idx < 1024; idx += 256) {
            int k = idx >> 5, i = idx & 31;
            w2s[k * 32 + i] = W2[i * 32 + k];
        }
        if (tid2 < 128) obssh[tid2] = obsv[blockIdx.x * ROWS_PER_CTA * 16 + tid2];
        for (int i = tid2; i < 2 * HBUF; i += 256) hsh[i] = 0.f;
        for (int i = tid2; i < ROWS_PER_CTA * TSTEPS; i += 256) {
            int o = BSZ * TSTEPS * 2 + blockIdx.x * ROWS_PER_CTA * TSTEPS + i;
            if (o < out_size) out[o] = 0.f;
        }
        BARSYNC(4);   // wcs + obssh visible within staging group
        // ---- W1C = W1 @ Wcomb, packed like old w1pk: entry [k4*32+i] ----
        for (int idx = tid2; idx < 512; idx += 256) {
            int k4 = idx >> 5, i = idx & 31;
            float acc0 = 0.f, acc1 = 0.f, acc2 = 0.f, acc3 = 0.f;
#pragma unroll 8
            for (int j = 0; j < 64; j++) {
                float wv = W1[i * 64 + j];
                const float* wr = wcs + j * WCSTRIDE + 4 * k4;
                acc0 = fmaf(wv, wr[0], acc0);
                acc1 = fmaf(wv, wr[1], acc1);
                acc2 = fmaf(wv, wr[2], acc2);
                acc3 = fmaf(wv, wr[3], acc3);
            }
            w1pk[k4 * 32 + i] = make_float4(acc0, acc1, acc2, acc3);
        }
        if (tid2 < 48) {
            int q = tid2 >> 4, rem = tid2 & 15, row = rem >> 1, c = rem & 1;
            ring[q * 16 + row * 2 + c] = obssh[row * 16 + 10 + q * 2 + c];
        }
    }

    // ---- per-thread mapping ----
    const int lane   = tid & 31;
    const int warp   = tid >> 5;
    const int rowGrp = warp >> 3;
    const int jslice = warp & 7;
    const int g      = lane >> 3;
    const int jj     = lane & 7;
    const int jglob  = jslice * 8 + jj;
    const int rowBase = rowGrp * 4;
    const int grow   = g * 64 + jglob;
    const int mh     = jslice >> 2;       // k-half for W1C
    const int rowW1  = rowBase + (jslice & 3);
    const int rowGlobW1 = blockIdx.x * ROWS_PER_CTA + rowW1;
    const int barid  = 1 + rowGrp;

    // ---- register-resident cell weights ----
    float4 wreg4[16];
    {
        const float4* wsrc = (const float4*)(Whh_o + grow * 64);
#pragma unroll
        for (int k4 = 0; k4 < 16; k4++) wreg4[k4] = wsrc[k4];
    }
    const float wx0  = Wih_o[grow * 2];
    const float wx1  = Wih_o[grow * 2 + 1];
    const float bsum = bih_o[grow] + bhh_o[grow];
    const float b2r  = b2[lane];
    const float w3r0 = W3[lane];
    const float w3r1 = W3[32 + lane];
    const float b30  = b3[0], b31 = b3[1];
    // unified activation: act(x) = aAct * tanh(bAct * x) + cAct
    const float aAct = (g == 2) ? 1.0f : 0.5f;
    const float bAct = (g == 2) ? 1.0f : 0.5f;
    const float cAct = (g == 2) ? 0.0f : 0.5f;
    const bool  t0   = (g & 1) != 0;
    const bool  t1   = (g & 2) != 0;

    __syncthreads();  // global join: t-scan + staging both complete

    // ---- t1c[s][i] = b1[i] + W1[i]·tcf[s]  (overlays wcs — dead after W1C fold) ----
    for (int idx = tid; idx < 2048; idx += CTA_THREADS) {
        int s = idx >> 5, i = idx & 31;
        float acc = b1[i];
#pragma unroll 8
        for (int j = 0; j < 64; j++)
            acc = fmaf(W1[i * 64 + j], tcf[s * 64 + j], acc);
        t1cs[idx] = acc;
    }
    __syncthreads();

    // =========================================================
    // Phase 3: main loop (two independent 256-thr groups)
    //   step s: B:[W1C·h(s) k-halves] bar  C:[tail -> y_s] bar  cell(s+1) bar
    // =========================================================
    int hp = 0;
    float c0 = 0.f, c1 = 0.f, c2 = 0.f, c3 = 0.f;

#define ROWSTEP(A, cvar, ridx)                                                    \
        {                                                                         \
            float a_ = fmaf(tanhap(bAct * (A)), aAct, cAct);                      \
            float v1_ = __shfl_xor_sync(0xffffffffu, a_, 8);                      \
            float v2_ = __shfl_xor_sync(0xffffffffu, a_, 16);                     \
            float v3_ = __shfl_xor_sync(0xffffffffu, v1_, 16);                    \
            float I_ = t1 ? (t0 ? v3_ : v2_) : (t0 ? v1_ : a_);                   \
            float F_ = t1 ? (t0 ? v2_ : v3_) : (t0 ? a_  : v1_);                  \
            float G_ = t1 ? (t0 ? v1_ : a_ ) : (t0 ? v3_ : v2_);                  \
            float O_ = t1 ? (t0 ? a_  : v1_) : (t0 ? v2_ : v3_);                  \
            cvar = fmaf(F_, cvar, I_ * G_);                                       \
            float h_ = O_ * tanhap(cvar);                                         \
            if (g == 0) hw[(rowBase + (ridx)) * HSTRIDE + jglob] = h_;            \
        }

    auto cell_core = [&](float x00, float x10, float x01, float x11,
                         float x02, float x12, float x03, float x13) {
        unsigned long long a0 = 0ull, a1 = 0ull, a2 = 0ull, a3 = 0ull;
        const ulonglong2* h40 = (const ulonglong2*)(hsh + hp * HBUF + (rowBase + 0) * HSTRIDE);
        const ulonglong2* h41 = (const ulonglong2*)(hsh + hp * HBUF + (rowBase + 1) * HSTRIDE);
        const ulonglong2* h42 = (const ulonglong2*)(hsh + hp * HBUF + (rowBase + 2) * HSTRIDE);
        const ulonglong2* h43 = (const ulonglong2*)(hsh + hp * HBUF + (rowBase + 3) * HSTRIDE);
        const ulonglong2* wp  = (const ulonglong2*)wreg4;
#pragma unroll
        for (int k4 = 0; k4 < 16; k4++) {
            ulonglong2 w = wp[k4];
            ulonglong2 v0 = h40[k4], v1 = h41[k4], v2 = h42[k4], v3 = h43[k4];
            fma2(a0, w.x, v0.x); fma2(a0, w.y, v0.y);
            fma2(a1, w.x, v1.x); fma2(a1, w.y, v1.y);
            fma2(a2, w.x, v2.x); fma2(a2, w.y, v2.y);
            fma2(a3, w.x, v3.x); fma2(a3, w.y, v3.y);
        }
        float2 f0 = upk(a0), f1 = upk(a1), f2 = upk(a2), f3 = upk(a3);
        float A0 = f0.x + f0.y + fmaf(wx0, x00, fmaf(wx1, x10, bsum));
        float A1 = f1.x + f1.y + fmaf(wx0, x01, fmaf(wx1, x11, bsum));
        float A2 = f2.x + f2.y + fmaf(wx0, x02, fmaf(wx1, x12, bsum));
        float A3 = f3.x + f3.y + fmaf(wx0, x03, fmaf(wx1, x13, bsum));
        float* hw = hsh + (hp ^ 1) * HBUF;
        ROWSTEP(A0, c0, 0) ROWSTEP(A1, c1, 1) ROWSTEP(A2, c2, 2) ROWSTEP(A3, c3, 3)
        hp ^= 1;
        BARSYNC(barid);
    };

    // ---- observation scan (8 steps) ----
#pragma unroll 1
    for (int t = 0; t < 8; t++) {
        cell_core(obssh[(rowBase + 0) * 16 + 2 * t], obssh[(rowBase + 0) * 16 + 2 * t + 1],
                  obssh[(rowBase + 1) * 16 + 2 * t], obssh[(rowBase + 1) * 16 + 2 * t + 1],
                  obssh[(rowBase + 2) * 16 + 2 * t], obssh[(rowBase + 2) * 16 + 2 * t + 1],
                  obssh[(rowBase + 3) * 16 + 2 * t], obssh[(rowBase + 3) * 16 + 2 * t + 1]);
    }

    // ---- autoregressive rollout ----
#pragma unroll 1
    for (int s = 0; s < TSTEPS; s++) {
        // ---- Phase B: s1 = (W1C·h(s)) k-half, dual packed accumulators ----
        float s1;
        {
            unsigned long long s1a = 0ull, s1b = 0ull;
            const ulonglong2* w1q = (const ulonglong2*)(w1pk + mh * 8 * 32);
            const ulonglong2* hr2 = (const ulonglong2*)(hsh + hp * HBUF + rowW1 * HSTRIDE) + mh * 8;
#pragma unroll
            for (int m4 = 0; m4 < 8; m4++) {
                ulonglong2 w = w1q[m4 * 32 + lane];
                ulonglong2 hv = hr2[m4];
                fma2(s1a, w.x, hv.x); fma2(s1b, w.y, hv.y);
            }
            float2 fa = upk(s1a), fb = upk(s1b);
            s1 = (fa.x + fa.y) + (fb.x + fb.y);
            if (mh) psum[rowW1 * 32 + lane] = s1;
        }
        BARSYNC(barid);
        // ---- Phase C: tail (mh0 warps only) -> y_s ----
        if (!mh) {
            float a = lrelu(s1 + psum[rowW1 * 32 + lane] + t1cs[s * 32 + lane]);
            float ta = b2r, tb = 0.f;
#pragma unroll
            for (int k = 0; k < 32; k += 2) {
                float ak0 = __shfl_sync(0xffffffffu, a, k);
                float ak1 = __shfl_sync(0xffffffffu, a, k + 1);
                ta = fmaf(w2s[k * 32 + lane], ak0, ta);
                tb = fmaf(w2s[(k + 1) * 32 + lane], ak1, tb);
            }
            float t = lrelu(ta + tb);
            float p0 = t * w3r0, p1 = t * w3r1;
#pragma unroll
            for (int off = 16; off > 0; off >>= 1) {
                p0 += __shfl_xor_sync(0xffffffffu, p0, off);
                p1 += __shfl_xor_sync(0xffffffffu, p1, off);
            }
            if (lane == 0) {
                int qn = ((s + 2) % 3) * 16 + rowW1 * 2;  // y_{s-1}
                int qo = (s % 3) * 16 + rowW1 * 2;        // y_{s-3} -> becomes y_s
                float bu2x = ring[qn], bu2y = ring[qn + 1];
                float b0x = ring[qo], b0y = ring[qo + 1];
                float yx = p0 + b30 + bu2x + (bu2x - b0x) * 0.5f;
                float yy = p1 + b31 + bu2y + (bu2y - b0y) * 0.5f;
                out[rowGlobW1 * (2 * TSTEPS) + s * 2]     = yx;
                out[rowGlobW1 * (2 * TSTEPS) + s * 2 + 1] = yy;
                ring[qo] = yx; ring[qo + 1] = yy;
            }
        }
        BARSYNC(barid);
        // ---- cell(s+1) fed by y_s ----
        if (s < TSTEPS - 1) {
            int q = (s % 3) * 16;   // slot now holding y_s
            cell_core(ring[q + (rowBase + 0) * 2], ring[q + (rowBase + 0) * 2 + 1],
                      ring[q + (rowBase + 1) * 2], ring[q + (rowBase + 1) * 2 + 1],
                      ring[q + (rowBase + 2) * 2], ring[q + (rowBase + 2) * 2 + 1],
                      ring[q + (rowBase + 3) * 2], ring[q + (rowBase + 3) * 2 + 1]);
        }
    }
#undef ROWSTEP
}

extern "C" void kernel_launch(void* const* d_in, const int* in_sizes, int n_in,
                              void* d_out, int out_size)
{
    const float* obsv  = (const float*)d_in[0];
    // d_in[1] = teom: unused (reference feeds zeros into the t-LSTM)
    const float* Wih_o = (const float*)d_in[2];
    const float* Whh_o = (const float*)d_in[3];
    const float* bih_o = (const float*)d_in[4];
    const float* bhh_o = (const float*)d_in[5];
    // d_in[6] = Wih_t: unused (x == 0)
    const float* Whh_t = (const float*)d_in[7];
    const float* bih_t = (const float*)d_in[8];
    const float* bhh_t = (const float*)d_in[9];
    const float* Wof   = (const float*)d_in[10];
    const float* bof   = (const float*)d_in[11];
    const float* Wtf   = (const float*)d_in[12];
    const float* btf   = (const float*)d_in[13];
    const float* Wmix  = (const float*)d_in[14];
    const float* bmix  = (const float*)d_in[15];
    const float* W1    = (const float*)d_in[16];
    const float* b1    = (const float*)d_in[17];
    const float* W2    = (const float*)d_in[18];
    const float* b2    = (const float*)d_in[19];
    const float* W3    = (const float*)d_in[20];
    const float* b3    = (const float*)d_in[21];

    cudaFuncSetAttribute(navnet_fused_kernel, cudaFuncAttributeMaxDynamicSharedMemorySize, SMEM_BYTES);
    navnet_fused_kernel<<<GRID_CTAS, CTA_THREADS, SMEM_BYTES>>>(
        obsv, Wih_o, Whh_o, bih_o, bhh_o,
        Whh_t, bih_t, bhh_t, Wof, bof, Wtf, btf, Wmix, bmix,
        W1, b1, W2, b2, W3, b3,
        (float*)d_out, out_size);
}

// round 17
// speedup vs baseline: 1.1671x; 1.1671x over previous
#include <cuda_runtime.h>

#define TSTEPS 64
#define BSZ 1024
#define ROWS_PER_CTA 8
#define CTA_THREADS 512
#define GRID_CTAS 128

// ---- smem offsets (bytes) ---- (NO overlay: t-phase and main phase disjoint)
#define OFF_WHHT   0        // float[64][256] 64KB   (t-phase)
#define OFF_TCF    65536    // float[64][64]  16KB   per-step t-const (persistent)
#define OFF_WTF    81920    // 16KB (t-phase)
#define OFF_WMT    98304    // 16KB (t-phase)
#define OFF_WMO    114688   // 16KB (t-phase, read by fold)
#define OFF_TSCR   131072   // 4KB  (t-phase scratch)
#define OFF_WCS    135168   // float[64*68] 17408B  Wcomb [j][k], row stride 68
#define OFF_W1PK   152576   // float4[512]  8KB
#define OFF_W2S    160768   // float[1024]  4KB
#define OFF_HSH    164864   // float[2][8][72] 4608B
#define OFF_MROW   169472   // float[8][72] 2304B
#define OFF_PSUM   171776   // float[8][32] 1KB
#define OFF_RING   172800   // float[3][8][2] 192B
#define OFF_OBS    172992   // float[8][16] 512B
#define SMEM_BYTES 173568

#define HSTRIDE 72
#define HBUF    576
#define WCSTRIDE 68
#define MSTRIDE 72

#define BARSYNC(id) asm volatile("bar.sync %0, 256;" :: "r"(id) : "memory")

__device__ __forceinline__ float sigf(float x) { return 1.0f / (1.0f + __expf(-x)); }
__device__ __forceinline__ float tanha(float x) { return 2.0f / (1.0f + __expf(-2.0f * x)) - 1.0f; }
__device__ __forceinline__ float lrelu(float v) { return v >= 0.0f ? v : 0.1f * v; }

// hardware tanh (single MUFU-class instruction, sm_75+)
__device__ __forceinline__ float tanhap(float x) {
    float y;
    asm("tanh.approx.f32 %0, %1;" : "=f"(y) : "f"(x));
    return y;
}

// packed f32x2 helpers (paired-k accumulation)
__device__ __forceinline__ void fma2(unsigned long long& a, unsigned long long w, unsigned long long h) {
    asm("fma.rn.f32x2 %0, %1, %2, %0;" : "+l"(a) : "l"(w), "l"(h));
}
__device__ __forceinline__ float2 upk(unsigned long long v) {
    float2 f;
    asm("mov.b64 {%0, %1}, %2;" : "=f"(f.x), "=f"(f.y) : "l"(v));
    return f;
}

__global__ void __launch_bounds__(CTA_THREADS, 1) navnet_fused_kernel(
    const float* __restrict__ obsv,
    const float* __restrict__ Wih_o, const float* __restrict__ Whh_o,
    const float* __restrict__ bih_o, const float* __restrict__ bhh_o,
    const float* __restrict__ Whh_t, const float* __restrict__ bih_t,
    const float* __restrict__ bhh_t, const float* __restrict__ Wof,
    const float* __restrict__ bof, const float* __restrict__ Wtf,
    const float* __restrict__ btf, const float* __restrict__ Wmix,
    const float* __restrict__ bmix,
    const float* __restrict__ W1, const float* __restrict__ b1,
    const float* __restrict__ W2, const float* __restrict__ b2,
    const float* __restrict__ W3, const float* __restrict__ b3,
    float* __restrict__ out, int out_size)
{
    extern __shared__ char smem[];
    const int tid = threadIdx.x;

    // t-phase pointers
    float*  WhhtT  = (float*)(smem + OFF_WHHT);
    float*  tcf    = (float*)(smem + OFF_TCF);
    float*  WtfT   = (float*)(smem + OFF_WTF);
    float*  WmixTT = (float*)(smem + OFF_WMT);
    float*  WmixOT = (float*)(smem + OFF_WMO);
    float*  tscr   = (float*)(smem + OFF_TSCR);
    float*  h_t    = tscr;
    float*  c_t    = tscr + 64;
    float*  gates  = tscr + 128;
    float*  tsv    = tscr + 384;
    float*  part   = tscr + 512;
    float*  btg    = tscr + 768;

    // main-phase pointers
    float*  wcs   = (float*)(smem + OFF_WCS);
    float4* w1pk  = (float4*)(smem + OFF_W1PK);
    float*  w2s   = (float*)(smem + OFF_W2S);
    float*  hsh   = (float*)(smem + OFF_HSH);
    float*  mrow  = (float*)(smem + OFF_MROW);
    float*  psum  = (float*)(smem + OFF_PSUM);
    float*  ring  = (float*)(smem + OFF_RING);
    float*  obssh = (float*)(smem + OFF_OBS);

    // =========================================================
    // Phase 1 (all 512): stage t-branch inputs
    // =========================================================
    for (int i = tid; i < 16384; i += CTA_THREADS) {
        int r = i >> 6, k = i & 63;
        WhhtT[k * 256 + r] = Whh_t[i];
    }
    for (int i = tid; i < 4096; i += CTA_THREADS) {
        int j = i >> 6, k = i & 63;
        WtfT[k * 64 + j]   = Wtf[i];
        WmixTT[k * 64 + j] = Wmix[j * 128 + k];
        WmixOT[k * 64 + j] = Wmix[j * 128 + 64 + k];
    }
    if (tid < 256) btg[tid] = bih_t[tid] + bhh_t[tid];
    if (tid < 64) { h_t[tid] = 0.f; c_t[tid] = 0.f; }
    float btf_r  = (tid < 64) ? btf[tid]  : 0.f;
    float bmix_r = (tid < 64) ? bmix[tid] : 0.f;
    __syncthreads();

    if (tid < 256) {
        int j = tid & 63, qt = tid >> 6;
        float p = 0.f;
#pragma unroll
        for (int q = 0; q < 16; q++)
            p = fmaf(WmixOT[(qt * 16 + q) * 64 + j], bof[qt * 16 + q], p);
        part[tid] = p;
    }
    __syncthreads();
    float bmixsum_r = 0.f;
    if (tid < 64)
        bmixsum_r = bmix_r + part[tid] + part[64 + tid] + part[128 + tid] + part[192 + tid];
    __syncthreads();

    // =========================================================
    // Phase 2 (SPLIT): warps 0-7 run t-scan; warps 8-15 stage main-phase smem
    // =========================================================
    if (tid < 256) {
        const float bt = btg[tid];
        const int j = tid & 63, qt = (tid >> 6) & 3;
        for (int s = 0; s < TSTEPS; s++) {
            // gates matvec with DUAL accumulators (chain 256 -> ~130 cyc)
            float aa = bt, ab = 0.f;
#pragma unroll 8
            for (int k = 0; k < 64; k += 2) {
                aa = fmaf(WhhtT[k * 256 + tid],       h_t[k],     aa);
                ab = fmaf(WhhtT[(k + 1) * 256 + tid], h_t[k + 1], ab);
            }
            gates[tid] = aa + ab;
            BARSYNC(3);
            if (tid < 64) {
                float i_ = sigf(gates[tid]), f_ = sigf(gates[64 + tid]);
                float g_ = tanha(gates[128 + tid]), o_ = sigf(gates[192 + tid]);
                float cn = f_ * c_t[tid] + i_ * g_;
                c_t[tid] = cn;
                h_t[tid] = o_ * tanha(cn);
            }
            BARSYNC(3);
            {
                float p = 0.f;
#pragma unroll
                for (int k = 0; k < 16; k++)
                    p = fmaf(WtfT[(qt * 16 + k) * 64 + j], h_t[qt * 16 + k], p);
                part[tid] = p;
            }
            BARSYNC(3);
            if (tid < 64) tsv[tid] = btf_r + part[tid] + part[64 + tid] + part[128 + tid] + part[192 + tid];
            BARSYNC(3);
            {
                float p = 0.f;
#pragma unroll
                for (int k = 0; k < 16; k++)
                    p = fmaf(WmixTT[(qt * 16 + k) * 64 + j], tsv[qt * 16 + k], p);
                part[tid] = p;
            }
            BARSYNC(3);
            if (tid < 64)
                tcf[s * 64 + tid] = bmixsum_r + part[tid] + part[64 + tid] + part[128 + tid] + part[192 + tid];
            // 6th barrier removed: next iteration's `part` writes happen only after
            // two BARSYNC(3)s, so the tcf-writer's reads of `part` are ordered.
        }
    } else {
        const int tid2 = tid - 256;
        for (int idx = tid2; idx < 4096; idx += 256) {
            int j = idx >> 6, k = idx & 63;
            float s = 0.f;
#pragma unroll 8
            for (int q = 0; q < 64; q++)
                s = fmaf(WmixOT[q * 64 + j], Wof[q * 64 + k], s);
            wcs[j * WCSTRIDE + k] = s;
        }
        for (int idx = tid2; idx < 512; idx += 256) {
            int m4 = idx >> 5, i = idx & 31;
            w1pk[m4 * 32 + i] = make_float4(W1[i * 64 + 4 * m4], W1[i * 64 + 4 * m4 + 1],
                                            W1[i * 64 + 4 * m4 + 2], W1[i * 64 + 4 * m4 + 3]);
        }
        for (int idx = tid2; idx < 1024; idx += 256) {
            int k = idx >> 5, i = idx & 31;
            w2s[k * 32 + i] = W2[i * 32 + k];
        }
        if (tid2 < 128) obssh[tid2] = obsv[blockIdx.x * ROWS_PER_CTA * 16 + tid2];
        for (int i = tid2; i < 2 * HBUF; i += 256) hsh[i] = 0.f;
        for (int i = tid2; i < ROWS_PER_CTA * TSTEPS; i += 256) {
            int o = BSZ * TSTEPS * 2 + blockIdx.x * ROWS_PER_CTA * TSTEPS + i;
            if (o < out_size) out[o] = 0.f;
        }
        BARSYNC(4);
        if (tid2 < 48) {
            int q = tid2 >> 4, rem = tid2 & 15, row = rem >> 1, c = rem & 1;
            ring[q * 16 + row * 2 + c] = obssh[row * 16 + 10 + q * 2 + c];
        }
    }

    // ---- per-thread mapping ----
    const int lane   = tid & 31;
    const int warp   = tid >> 5;
    const int rowGrp = warp >> 3;
    const int jslice = warp & 7;
    const int g      = lane >> 3;
    const int jj     = lane & 7;
    const int jglob  = jslice * 8 + jj;
    const int rowBase = rowGrp * 4;
    const int grow   = g * 64 + jglob;
    const int mh     = jslice >> 2;
    const int rowW1  = rowBase + (jslice & 3);
    const int rowGlobW1 = blockIdx.x * ROWS_PER_CTA + rowW1;
    const int barid  = 1 + rowGrp;

    // ---- register-resident cell weights ----
    float4 wreg4[16];
    {
        const float4* wsrc = (const float4*)(Whh_o + grow * 64);
#pragma unroll
        for (int k4 = 0; k4 < 16; k4++) wreg4[k4] = wsrc[k4];
    }
    const float wx0  = Wih_o[grow * 2];
    const float wx1  = Wih_o[grow * 2 + 1];
    const float bsum = bih_o[grow] + bhh_o[grow];
    const float b1r  = b1[lane];
    const float b2r  = b2[lane];
    const float w3r0 = W3[lane];
    const float w3r1 = W3[32 + lane];
    const float b30  = b3[0], b31 = b3[1];
    // unified activation: act(x) = aAct * tanh(bAct * x) + cAct
    const float aAct = (g == 2) ? 1.0f : 0.5f;
    const float bAct = (g == 2) ? 1.0f : 0.5f;
    const float cAct = (g == 2) ? 0.0f : 0.5f;
    const bool  t0   = (g & 1) != 0;
    const bool  t1   = (g & 2) != 0;

    __syncthreads();  // global join: t-scan + staging both complete

    // =========================================================
    // Phase 3: main loop (two independent 256-thr groups), paired-k FFMA2
    // =========================================================
    int hp = 0;
    float c0 = 0.f, c1 = 0.f, c2 = 0.f, c3 = 0.f;

#define ROWSTEP(A, cvar, ridx)                                                    \
        {                                                                         \
            float a_ = fmaf(tanhap(bAct * (A)), aAct, cAct);                      \
            float v1_ = __shfl_xor_sync(0xffffffffu, a_, 8);                      \
            float v2_ = __shfl_xor_sync(0xffffffffu, a_, 16);                     \
            float v3_ = __shfl_xor_sync(0xffffffffu, v1_, 16);                    \
            float I_ = t1 ? (t0 ? v3_ : v2_) : (t0 ? v1_ : a_);                   \
            float F_ = t1 ? (t0 ? v2_ : v3_) : (t0 ? a_  : v1_);                  \
            float G_ = t1 ? (t0 ? v1_ : a_ ) : (t0 ? v3_ : v2_);                  \
            float O_ = t1 ? (t0 ? a_  : v1_) : (t0 ? v2_ : v3_);                  \
            cvar = fmaf(F_, cvar, I_ * G_);                                       \
            float h_ = O_ * tanhap(cvar);                                         \
            if (g == 0) hw[(rowBase + (ridx)) * HSTRIDE + jglob] = h_;            \
        }

    auto cell_core = [&](float x00, float x10, float x01, float x11,
                         float x02, float x12, float x03, float x13) {
        unsigned long long a0 = 0ull, a1 = 0ull, a2 = 0ull, a3 = 0ull;
        const ulonglong2* h40 = (const ulonglong2*)(hsh + hp * HBUF + (rowBase + 0) * HSTRIDE);
        const ulonglong2* h41 = (const ulonglong2*)(hsh + hp * HBUF + (rowBase + 1) * HSTRIDE);
        const ulonglong2* h42 = (const ulonglong2*)(hsh + hp * HBUF + (rowBase + 2) * HSTRIDE);
        const ulonglong2* h43 = (const ulonglong2*)(hsh + hp * HBUF + (rowBase + 3) * HSTRIDE);
        const ulonglong2* wp  = (const ulonglong2*)wreg4;
#pragma unroll
        for (int k4 = 0; k4 < 16; k4++) {
            ulonglong2 w = wp[k4];
            ulonglong2 v0 = h40[k4], v1 = h41[k4], v2 = h42[k4], v3 = h43[k4];
            fma2(a0, w.x, v0.x); fma2(a0, w.y, v0.y);
            fma2(a1, w.x, v1.x); fma2(a1, w.y, v1.y);
            fma2(a2, w.x, v2.x); fma2(a2, w.y, v2.y);
            fma2(a3, w.x, v3.x); fma2(a3, w.y, v3.y);
        }
        float2 f0 = upk(a0), f1 = upk(a1), f2 = upk(a2), f3 = upk(a3);
        float A0 = f0.x + f0.y + fmaf(wx0, x00, fmaf(wx1, x10, bsum));
        float A1 = f1.x + f1.y + fmaf(wx0, x01, fmaf(wx1, x11, bsum));
        float A2 = f2.x + f2.y + fmaf(wx0, x02, fmaf(wx1, x12, bsum));
        float A3 = f3.x + f3.y + fmaf(wx0, x03, fmaf(wx1, x13, bsum));
        float* hw = hsh + (hp ^ 1) * HBUF;
        ROWSTEP(A0, c0, 0) ROWSTEP(A1, c1, 1) ROWSTEP(A2, c2, 2) ROWSTEP(A3, c3, 3)
        hp ^= 1;
        BARSYNC(barid);
    };

    auto mix = [&](int s) {
        const int mrw = rowBase + g;
        // DUAL packed accumulators (chain 128 -> 64 cyc)
        unsigned long long m0 = 0ull, m1 = 0ull;
        const ulonglong2* wc2p = (const ulonglong2*)(wcs + jglob * WCSTRIDE);
        const ulonglong2* h2m  = (const ulonglong2*)(hsh + hp * HBUF + mrw * HSTRIDE);
#pragma unroll
        for (int k4 = 0; k4 < 16; k4++) {
            ulonglong2 w = wc2p[k4];
            ulonglong2 v = h2m[k4];
            fma2(m0, w.x, v.x); fma2(m1, w.y, v.y);
        }
        float2 mf0 = upk(m0), mf1 = upk(m1);
        mrow[mrw * MSTRIDE + jglob] = tcf[s * 64 + jglob] + ((mf0.x + mf0.y) + (mf1.x + mf1.y));
        BARSYNC(barid);
        // W1: warp handles (rowW1, mh), lane = i, dual packed accumulators
        unsigned long long s1a = 0ull, s1b = 0ull;
        {
            const ulonglong2* w1q = (const ulonglong2*)(w1pk + mh * 8 * 32);
            const ulonglong2* mr2 = (const ulonglong2*)(mrow + rowW1 * MSTRIDE) + mh * 8;
#pragma unroll
            for (int m4 = 0; m4 < 8; m4++) {
                ulonglong2 w = w1q[m4 * 32 + lane];
                ulonglong2 mv = mr2[m4];
                fma2(s1a, w.x, mv.x); fma2(s1b, w.y, mv.y);
            }
        }
        float2 fa = upk(s1a), fb = upk(s1b);
        float s1 = (fa.x + fa.y) + (fb.x + fb.y);
        if (mh) psum[rowW1 * 32 + lane] = s1;
        BARSYNC(barid);
        if (!mh) {
            float a = lrelu(s1 + psum[rowW1 * 32 + lane] + b1r);
            // W2 tail with DUAL accumulators (chain 128 -> 64 cyc)
            float ta = b2r, tb = 0.f;
#pragma unroll
            for (int k = 0; k < 32; k += 2) {
                float ak0 = __shfl_sync(0xffffffffu, a, k);
                float ak1 = __shfl_sync(0xffffffffu, a, k + 1);
                ta = fmaf(w2s[k * 32 + lane], ak0, ta);
                tb = fmaf(w2s[(k + 1) * 32 + lane], ak1, tb);
            }
            float t = lrelu(ta + tb);
            float p0 = t * w3r0, p1 = t * w3r1;
#pragma unroll
            for (int off = 16; off > 0; off >>= 1) {
                p0 += __shfl_xor_sync(0xffffffffu, p0, off);
                p1 += __shfl_xor_sync(0xffffffffu, p1, off);
            }
            if (lane == 0) {
                int qn = ((s + 2) % 3) * 16 + rowW1 * 2;  // y_{s-1}
                int qo = (s % 3) * 16 + rowW1 * 2;        // y_{s-3}
                float bu2x = ring[qn], bu2y = ring[qn + 1];
                float b0x = ring[qo], b0y = ring[qo + 1];
                float yx = p0 + b30 + bu2x + (bu2x - b0x) * 0.5f;
                float yy = p1 + b31 + bu2y + (bu2y - b0y) * 0.5f;
                out[rowGlobW1 * (2 * TSTEPS) + s * 2]     = yx;
                out[rowGlobW1 * (2 * TSTEPS) + s * 2 + 1] = yy;
                ring[qo] = yx; ring[qo + 1] = yy;
            }
        }
        BARSYNC(barid);
    };

    // ---- observation scan (8 steps) ----
#pragma unroll 1
    for (int t = 0; t < 8; t++) {
        cell_core(obssh[(rowBase + 0) * 16 + 2 * t], obssh[(rowBase + 0) * 16 + 2 * t + 1],
                  obssh[(rowBase + 1) * 16 + 2 * t], obssh[(rowBase + 1) * 16 + 2 * t + 1],
                  obssh[(rowBase + 2) * 16 + 2 * t], obssh[(rowBase + 2) * 16 + 2 * t + 1],
                  obssh[(rowBase + 3) * 16 + 2 * t], obssh[(rowBase + 3) * 16 + 2 * t + 1]);
    }

    // ---- autoregressive rollout ----
    mix(0);
#pragma unroll 1
    for (int s = 1; s < TSTEPS; s++) {
        int q = ((s - 1) % 3) * 16;   // slot holding y_{s-1}
        cell_core(ring[q + (rowBase + 0) * 2], ring[q + (rowBase + 0) * 2 + 1],
                  ring[q + (rowBase + 1) * 2], ring[q + (rowBase + 1) * 2 + 1],
                  ring[q + (rowBase + 2) * 2], ring[q + (rowBase + 2) * 2 + 1],
                  ring[q + (rowBase + 3) * 2], ring[q + (rowBase + 3) * 2 + 1]);
        mix(s);
    }
#undef ROWSTEP
}

extern "C" void kernel_launch(void* const* d_in, const int* in_sizes, int n_in,
                              void* d_out, int out_size)
{
    const float* obsv  = (const float*)d_in[0];
    // d_in[1] = teom: unused (reference feeds zeros into the t-LSTM)
    const float* Wih_o = (const float*)d_in[2];
    const float* Whh_o = (const float*)d_in[3];
    const float* bih_o = (const float*)d_in[4];
    const float* bhh_o = (const float*)d_in[5];
    // d_in[6] = Wih_t: unused (x == 0)
    const float* Whh_t = (const float*)d_in[7];
    const float* bih_t = (const float*)d_in[8];
    const float* bhh_t = (const float*)d_in[9];
    const float* Wof   = (const float*)d_in[10];
    const float* bof   = (const float*)d_in[11];
    const float* Wtf   = (const float*)d_in[12];
    const float* btf   = (const float*)d_in[13];
    const float* Wmix  = (const float*)d_in[14];
    const float* bmix  = (const float*)d_in[15];
    const float* W1    = (const float*)d_in[16];
    const float* b1    = (const float*)d_in[17];
    const float* W2    = (const float*)d_in[18];
    const float* b2    = (const float*)d_in[19];
    const float* W3    = (const float*)d_in[20];
    const float* b3    = (const float*)d_in[21];

    cudaFuncSetAttribute(navnet_fused_kernel, cudaFuncAttributeMaxDynamicSharedMemorySize, SMEM_BYTES);
    navnet_fused_kernel<<<GRID_CTAS, CTA_THREADS, SMEM_BYTES>>>(
        obsv, Wih_o, Whh_o, bih_o, bhh_o,
        Whh_t, bih_t, bhh_t, Wof, bof, Wtf, btf, Wmix, bmix,
        W1, b1, W2, b2, W3, b3,
        (float*)d_out, out_size);
}